// round 16
// baseline (speedup 1.0000x reference)
#include <cuda_runtime.h>
#include <math.h>
#include <stdint.h>

#define TSEQ   2048
#define DMODEL 2048
#define NHEADS 16
#define HDIM   128
#define BATCH  2
#define QKVW   (DMODEL + 2*HDIM)   // 2304
#define MROWS  (BATCH*TSEQ)        // 4096

__device__ float g_qkv   [(size_t)BATCH * TSEQ * QKVW];
__device__ float g_attn  [(size_t)BATCH * TSEQ * DMODEL];
__device__ float g_xr    [(size_t)BATCH * TSEQ * DMODEL];
__device__ float g_vT    [(size_t)BATCH * HDIM * TSEQ];
__device__ float g_wqkv_t[(size_t)QKVW * DMODEL];
__device__ float g_wout_t[(size_t)DMODEL * DMODEL];

// ---------------------------------------------------------------------------
__device__ __forceinline__ uint32_t smem_u32(const void* p) {
    uint32_t a;
    asm("{ .reg .u64 t; cvta.to.shared.u64 t, %1; cvt.u32.u64 %0, t; }"
        : "=r"(a) : "l"(p));
    return a;
}
__device__ __forceinline__ float to_tf32(float x) {
    uint32_t u;
    asm("cvt.rna.tf32.f32 %0, %1;" : "=r"(u) : "f"(x));
    return __uint_as_float(u);
}
__device__ __forceinline__ uint32_t to_tf32_bits(float x) {
    uint32_t u;
    asm("cvt.rna.tf32.f32 %0, %1;" : "=r"(u) : "f"(x));
    return u;
}
__device__ __forceinline__ void mma_m16n8k8_tf32(float* c, const uint32_t* a,
                                                 uint32_t b0, uint32_t b1) {
    asm volatile(
        "mma.sync.aligned.m16n8k8.row.col.f32.tf32.tf32.f32 "
        "{%0,%1,%2,%3}, {%4,%5,%6,%7}, {%8,%9}, {%0,%1,%2,%3};"
        : "+f"(c[0]), "+f"(c[1]), "+f"(c[2]), "+f"(c[3])
        : "r"(a[0]), "r"(a[1]), "r"(a[2]), "r"(a[3]), "r"(b0), "r"(b1));
}
__device__ __forceinline__ void ldsm_x4(uint32_t* r, uint32_t addr) {
    asm volatile("ldmatrix.sync.aligned.m8n8.x4.shared.b16 {%0,%1,%2,%3}, [%4];"
                 : "=r"(r[0]), "=r"(r[1]), "=r"(r[2]), "=r"(r[3]) : "r"(addr));
}

#define MBAR_INIT(a, n) \
    asm volatile("mbarrier.init.shared.b64 [%0], %1;" :: "r"(a), "r"(n) : "memory")
#define MBAR_ARRIVE(a) \
    asm volatile("mbarrier.arrive.shared.b64 _, [%0];" :: "r"(a) : "memory")
#define MBAR_WAIT(a, ph) do { \
    uint32_t _m = (a), _p = (ph), _d; \
    asm volatile("{ .reg .pred p; mbarrier.try_wait.parity.acquire.cta.shared::cta.b64 p, [%1], %2; selp.b32 %0,1,0,p; }" \
                 : "=r"(_d) : "r"(_m), "r"(_p) : "memory"); \
    if (!_d) { \
        asm volatile("{ .reg .pred P1; WL_%=: mbarrier.try_wait.parity.acquire.cta.shared::cta.b64 P1, [%0], %1, 0x989680; @P1 bra.uni WD_%=; bra.uni WL_%=; WD_%=: }" \
                     :: "r"(_m), "r"(_p) : "memory"); \
    } \
} while (0)
#define CPASYNC_MBAR_ARRIVE(a) \
    asm volatile("cp.async.mbarrier.arrive.noinc.shared.b64 [%0];" :: "r"(a) : "memory")

// ---------------------------------------------------------------------------
// Merged prep: Wqkv transpose (blocks 0..4607), Wout transpose (4608..8703),
// x rounding (8704..16895). Block (32,8).
// ---------------------------------------------------------------------------
__global__ void prep_all(const float* __restrict__ Wqkv, float* __restrict__ wqkv_t,
                         const float* __restrict__ Wout, float* __restrict__ wout_t,
                         const float* __restrict__ x, float* __restrict__ xr)
{
    __shared__ float t[32][33];
    const int blk = blockIdx.x;
    const int tx = threadIdx.x, ty = threadIdx.y;

    if (blk < 4608) {          // Wqkv^T: [2048, 2304] -> [2304, 2048]
        int n0 = (blk % 72) * 32, k0 = (blk / 72) * 32;
#pragma unroll
        for (int r = 0; r < 32; r += 8)
            t[ty + r][tx] = Wqkv[(size_t)(k0 + ty + r) * QKVW + n0 + tx];
        __syncthreads();
#pragma unroll
        for (int r = 0; r < 32; r += 8)
            wqkv_t[(size_t)(n0 + ty + r) * DMODEL + k0 + tx] = to_tf32(t[tx][ty + r]);
    } else if (blk < 8704) {   // Wout^T: [2048, 2048]
        int b2 = blk - 4608;
        int n0 = (b2 % 64) * 32, k0 = (b2 / 64) * 32;
#pragma unroll
        for (int r = 0; r < 32; r += 8)
            t[ty + r][tx] = Wout[(size_t)(k0 + ty + r) * DMODEL + n0 + tx];
        __syncthreads();
#pragma unroll
        for (int r = 0; r < 32; r += 8)
            wout_t[(size_t)(n0 + ty + r) * DMODEL + k0 + tx] = to_tf32(t[tx][ty + r]);
    } else {                   // x rounding: 2M float4
        int i = (blk - 8704) * 256 + ty * 32 + tx;
        float4 v = ((const float4*)x)[i];
        v.x = to_tf32(v.x); v.y = to_tf32(v.y);
        v.z = to_tf32(v.z); v.w = to_tf32(v.w);
        ((float4*)xr)[i] = v;
    }
}

// ---------------------------------------------------------------------------
// mma.sync tf32 GEMM: 128 threads, 4 warps (2x2), warp tile 64x64.
// Fragment traffic per CTA-iter: 64KB (vs 96KB for 8x 32x64 warps).
// 3-stage mbarrier pipeline. Template on epilogue only.
//  FUSED=false: plain epilogue, plain B-col map (wn*64 + p*16).
//  FUSED=true : rope (bn<rope_lim), V tile -> vT (bn==vt_col), rounded stores;
//               split-32 B-col map so rope pairs (i,i+64) are thread-local.
// ---------------------------------------------------------------------------
#define BK 32
#define AS_STRIDE 36
#define TILE_FLOATS (128 * AS_STRIDE)
#define TILE_BYTES  (TILE_FLOATS * 4)
#define NSTAGE 3
#define GEMM_SMEM (2 * NSTAGE * TILE_BYTES + 64)

template<bool FUSED>
__global__ __launch_bounds__(128, 2) void gemm_mma_tf32(
    const float* __restrict__ A, const float* __restrict__ Bt,
    float* __restrict__ C,
    const float* __restrict__ sinp, const float* __restrict__ cosp,
    float* __restrict__ vTout,
    int M, int N, int K, int rope_lim, int vt_col)
{
    extern __shared__ float smf[];
    const uint32_t sm0 = smem_u32(smf);
    const uint32_t mb0 = sm0 + 2 * NSTAGE * TILE_BYTES;

    const int tid  = threadIdx.x;
    const int wid  = tid >> 5, lane = tid & 31;
    const int wm   = wid >> 1, wn = wid & 1;
    const int lr   = lane >> 2, lc = lane & 3;
    const int bm   = blockIdx.y * 128, bn = blockIdx.x * 128;
    const int NC   = K / BK;

    if (tid == 0) {
#pragma unroll
        for (int s = 0; s < NSTAGE; s++) {
            MBAR_INIT(mb0 + s * 8, 128);
            MBAR_INIT(mb0 + 24 + s * 8, 4);
        }
    }
    __syncthreads();

    // A ldsm offsets: rows wm*64 + p*16
    uint32_t aOff[4];
#pragma unroll
    for (int p = 0; p < 4; p++)
        aOff[p] = ((uint32_t)((wm * 64 + p * 16 + (lane & 7) + ((lane >> 3) & 1) * 8)
                   * AS_STRIDE + (lane >> 4) * 4)) * 4;
    // B ldsm offsets
    uint32_t bOff[4];
#pragma unroll
    for (int p = 0; p < 4; p++) {
        int rb = FUSED ? (wn * 32 + (p & 1) * 16 + (p >> 1) * 64)
                       : (wn * 64 + p * 16);
        bOff[p] = ((uint32_t)((rb + (lane & 7) + ((lane >> 4) & 1) * 8)
                   * AS_STRIDE + ((lane >> 3) & 1) * 4)) * 4;
    }

    float acc[4][8][4];
#pragma unroll
    for (int i = 0; i < 4; i++)
#pragma unroll
        for (int j = 0; j < 8; j++)
#pragma unroll
            for (int q = 0; q < 4; q++) acc[i][j][q] = 0.f;

    const int ldrow = tid >> 3, ldc4 = tid & 7;   // 16 rows / iter
    auto produce = [&](int s, int k0) {
        uint32_t sA = sm0 + s * TILE_BYTES;
        uint32_t sB = sm0 + (NSTAGE + s) * TILE_BYTES;
#pragma unroll
        for (int it = 0; it < 8; it++) {
            int row = it * 16 + ldrow;
            const float* g = A + (size_t)(bm + row) * K + k0 + ldc4 * 4;
            asm volatile("cp.async.cg.shared.global [%0], [%1], 16;"
                         :: "r"(sA + (uint32_t)(row * 144 + ldc4 * 16)), "l"(g));
        }
#pragma unroll
        for (int it = 0; it < 8; it++) {
            int row = it * 16 + ldrow;
            const float* g = Bt + (size_t)(bn + row) * K + k0 + ldc4 * 4;
            asm volatile("cp.async.cg.shared.global [%0], [%1], 16;"
                         :: "r"(sB + (uint32_t)(row * 144 + ldc4 * 16)), "l"(g));
        }
        CPASYNC_MBAR_ARRIVE(mb0 + s * 8);
    };

    produce(0, 0);
    produce(1, BK);
    produce(2, 2 * BK);

    int s = 0, ph = 0;
    for (int c = 0; c < NC; c++) {
        MBAR_WAIT(mb0 + s * 8, (uint32_t)ph);

        const uint32_t aBase = sm0 + s * TILE_BYTES;
        const uint32_t bBase = sm0 + (NSTAGE + s) * TILE_BYTES;
#pragma unroll
        for (int ks = 0; ks < 4; ks++) {
            uint32_t a[4][4], bb[16];
#pragma unroll
            for (int p = 0; p < 4; p++)
                ldsm_x4(a[p], aBase + aOff[p] + ks * 32);
#pragma unroll
            for (int p = 0; p < 4; p++)
                ldsm_x4(&bb[4 * p], bBase + bOff[p] + ks * 32);
#pragma unroll
            for (int mt = 0; mt < 4; mt++)
#pragma unroll
                for (int nt = 0; nt < 8; nt++)
                    mma_m16n8k8_tf32(acc[mt][nt], a[mt], bb[2 * nt], bb[2 * nt + 1]);
        }
        if (lane == 0) MBAR_ARRIVE(mb0 + 24 + s * 8);

        if (c + NSTAGE < NC) {
            MBAR_WAIT(mb0 + 24 + s * 8, (uint32_t)ph);
            produce(s, (c + NSTAGE) * BK);
        }
        s++; if (s == NSTAGE) { s = 0; ph ^= 1; }
    }

    // ---------------- epilogue ----------------
    if (!FUSED) {
#pragma unroll
        for (int mt = 0; mt < 4; mt++) {
            int row = bm + wm * 64 + mt * 16 + lr;
#pragma unroll
            for (int nt = 0; nt < 8; nt++) {
                int col = bn + wn * 64 + nt * 8 + lc * 2;
                *(float2*)(C + (size_t)row * N + col) =
                    make_float2(acc[mt][nt][0], acc[mt][nt][1]);
                *(float2*)(C + (size_t)(row + 8) * N + col) =
                    make_float2(acc[mt][nt][2], acc[mt][nt][3]);
            }
        }
        return;
    }

    if (bn == vt_col) {
        __syncthreads();
        float* st = smf;   // [128 cols][136]
#pragma unroll
        for (int mt = 0; mt < 4; mt++) {
            int r0l = wm * 64 + mt * 16 + lr;
#pragma unroll
            for (int nt = 0; nt < 8; nt++) {
                int cl = wn * 32 + (nt >> 2) * 64 + ((nt >> 1) & 1) * 16
                         + (nt & 1) * 8 + lc * 2;
                st[cl * 136 + r0l]           = to_tf32(acc[mt][nt][0]);
                st[(cl + 1) * 136 + r0l]     = to_tf32(acc[mt][nt][1]);
                st[cl * 136 + r0l + 8]       = to_tf32(acc[mt][nt][2]);
                st[(cl + 1) * 136 + r0l + 8] = to_tf32(acc[mt][nt][3]);
            }
        }
        __syncthreads();
        const int bb_ = bm / TSEQ;
        const int t0 = bm & (TSEQ - 1);
#pragma unroll
        for (int it = 0; it < 32; it++) {
            int d = it * 4 + (tid >> 5);
            int t4 = (tid & 31) * 4;
            float4 v = *(float4*)&st[d * 136 + t4];
            *(float4*)&vTout[((size_t)bb_ * HDIM + d) * TSEQ + t0 + t4] = v;
        }
        return;
    }

    if (bn < rope_lim) {
#pragma unroll
        for (int mt = 0; mt < 4; mt++) {
            int row0 = bm + wm * 64 + mt * 16 + lr;
            int tA = row0 & (TSEQ - 1);
            int tB = (row0 + 8) & (TSEQ - 1);
#pragma unroll
            for (int nt = 0; nt < 4; nt++) {
                int i0 = wn * 32 + ((nt >> 1) & 1) * 16 + (nt & 1) * 8 + lc * 2;
                float2 sA = *(const float2*)&sinp[tA * 64 + i0];
                float2 cA = *(const float2*)&cosp[tA * 64 + i0];
                float2 sB = *(const float2*)&sinp[tB * 64 + i0];
                float2 cB = *(const float2*)&cosp[tB * 64 + i0];
                float x1, x2;
                x1 = acc[mt][nt][0]; x2 = acc[mt][nt + 4][0];
                acc[mt][nt][0]     = x1 * cA.x - x2 * sA.x;
                acc[mt][nt + 4][0] = x2 * cA.x + x1 * sA.x;
                x1 = acc[mt][nt][1]; x2 = acc[mt][nt + 4][1];
                acc[mt][nt][1]     = x1 * cA.y - x2 * sA.y;
                acc[mt][nt + 4][1] = x2 * cA.y + x1 * sA.y;
                x1 = acc[mt][nt][2]; x2 = acc[mt][nt + 4][2];
                acc[mt][nt][2]     = x1 * cB.x - x2 * sB.x;
                acc[mt][nt + 4][2] = x2 * cB.x + x1 * sB.x;
                x1 = acc[mt][nt][3]; x2 = acc[mt][nt + 4][3];
                acc[mt][nt][3]     = x1 * cB.y - x2 * sB.y;
                acc[mt][nt + 4][3] = x2 * cB.y + x1 * sB.y;
            }
        }
    }

#pragma unroll
    for (int mt = 0; mt < 4; mt++) {
        int row = bm + wm * 64 + mt * 16 + lr;
#pragma unroll
        for (int nt = 0; nt < 8; nt++) {
            int col = bn + wn * 32 + (nt >> 2) * 64
                      + ((nt >> 1) & 1) * 16 + (nt & 1) * 8 + lc * 2;
            *(float2*)(C + (size_t)row * N + col) =
                make_float2(to_tf32(acc[mt][nt][0]), to_tf32(acc[mt][nt][1]));
            *(float2*)(C + (size_t)(row + 8) * N + col) =
                make_float2(to_tf32(acc[mt][nt][2]), to_tf32(acc[mt][nt][3]));
        }
    }
}

// ---------------------------------------------------------------------------
// Flash attention (round-15 version, unchanged).
// ---------------------------------------------------------------------------
#define QTL 64
#define KTL 64
#define QST 132
#define VST 68
#define ATT_Q_OFF   0
#define ATT_K_OFF   (QTL * QST)
#define ATT_V_OFF   (2 * QTL * QST)
#define ATT_DOC_OFF (2 * QTL * QST + HDIM * VST)
#define ATT_SMEM_BYTES ((ATT_DOC_OFF + 132) * 4)

__global__ __launch_bounds__(128, 2) void attn_mma(
    const float* __restrict__ qkv, const float* __restrict__ vT,
    const int* __restrict__ doc, float* __restrict__ outa)
{
    extern __shared__ float smf[];
    int* docq  = (int*)(smf + ATT_DOC_OFF);
    int* dock  = docq + 64;
    int* skst  = dock + 64;

    const int tid = threadIdx.x;
    const int wid = tid >> 5, lane = tid & 31;
    const int lr = lane >> 2, lc = lane & 3;
    const int qt = blockIdx.x, h = blockIdx.y, b = blockIdx.z;
    const int q0 = qt * QTL;
    const float* qbase = qkv + (size_t)b * TSEQ * QKVW;
    const float* vbase = vT + (size_t)b * HDIM * TSEQ;
    const float SCALE = 0.08838834764831845f;

    const uint32_t sm0 = smem_u32(smf);
    const uint32_t QsB = sm0 + ATT_Q_OFF * 4;
    const uint32_t KtB = sm0 + ATT_K_OFF * 4;
    const uint32_t VtB = sm0 + ATT_V_OFF * 4;

    const uint32_t qOff = ((uint32_t)((wid * 16 + (lane & 7) + ((lane >> 3) & 1) * 8)
                           * QST + (lane >> 4) * 4)) * 4;
    uint32_t kOff[4];
#pragma unroll
    for (int p = 0; p < 4; p++)
        kOff[p] = ((uint32_t)((p * 16 + (lane & 7) + ((lane >> 4) & 1) * 8)
                   * QST + ((lane >> 3) & 1) * 4)) * 4;
    uint32_t vOff[8];
#pragma unroll
    for (int p = 0; p < 8; p++)
        vOff[p] = ((uint32_t)((p * 16 + (lane & 7) + ((lane >> 4) & 1) * 8)
                   * VST + ((lane >> 3) & 1) * 4)) * 4;

    const int sl1 = lr * 4 + (lc >> 1);
    const int sl2 = sl1 + 2;
    const bool odd = (lc & 1);

    const int qkRow = tid >> 5, qkChunk = (tid & 31);
    const int vRow = tid >> 4,  vChunk = (tid & 15);

#pragma unroll
    for (int r = 0; r < 16; r++) {
        int row = r * 4 + qkRow;
        const float* g = qbase + (size_t)(q0 + row) * QKVW + h * HDIM + qkChunk * 4;
        asm volatile("cp.async.cg.shared.global [%0], [%1], 16;"
                     :: "r"(QsB + (uint32_t)(row * (QST * 4) + qkChunk * 16)), "l"(g));
    }
    asm volatile("cp.async.commit_group;" ::: "memory");

    if (tid < 64) docq[tid] = doc[b * TSEQ + q0 + tid];
    if (tid == 0) {
        int d0 = doc[b * TSEQ + q0];
        int lo = 0, hi = q0;
        while (lo < hi) {
            int mid = (lo + hi) >> 1;
            if (doc[b * TSEQ + mid] < d0) lo = mid + 1; else hi = mid;
        }
        skst[0] = lo >> 6;
    }
    asm volatile("cp.async.wait_group 0;" ::: "memory");
    __syncthreads();

    const int kt_start = skst[0];
    const int r0g = q0 + wid * 16 + lr;
    const int r1g = r0g + 8;
    const int dq0 = docq[wid * 16 + lr];
    const int dq1 = docq[wid * 16 + lr + 8];
    const int dqFirst = docq[0], dqLast = docq[QTL - 1];

    auto issueK = [&](int kt) {
        const int k0 = kt * KTL;
#pragma unroll
        for (int r = 0; r < 16; r++) {
            int row = r * 4 + qkRow;
            const float* g = qbase + (size_t)(k0 + row) * QKVW + DMODEL + qkChunk * 4;
            asm volatile("cp.async.cg.shared.global [%0], [%1], 16;"
                         :: "r"(KtB + (uint32_t)(row * (QST * 4) + qkChunk * 16)), "l"(g));
        }
    };
    auto issueV = [&](int kt) {
        const int k0 = kt * KTL;
#pragma unroll
        for (int r = 0; r < 16; r++) {
            int d = r * 8 + vRow;
            const float* g = vbase + (size_t)d * TSEQ + k0 + vChunk * 4;
            asm volatile("cp.async.cg.shared.global [%0], [%1], 16;"
                         :: "r"(VtB + (uint32_t)(d * (VST * 4) + vChunk * 16)), "l"(g));
        }
    };

    float m0 = -1e30f, m1 = -1e30f, l0 = 0.f, l1 = 0.f;
    float O[16][4];
#pragma unroll
    for (int nt = 0; nt < 16; nt++)
#pragma unroll
        for (int q = 0; q < 4; q++) O[nt][q] = 0.f;

    issueK(kt_start);
    asm volatile("cp.async.commit_group;" ::: "memory");
    issueV(kt_start);
    asm volatile("cp.async.commit_group;" ::: "memory");

    for (int kt = kt_start; kt <= qt; kt++) {
        const int k0tok = kt * KTL;
        const bool diag = (kt == qt);

        if (tid < 64) dock[tid] = doc[b * TSEQ + k0tok + tid];

        asm volatile("cp.async.wait_group 1;" ::: "memory");
        __syncthreads();

        float S[8][4];
        uint32_t* Su = (uint32_t*)S;
#pragma unroll
        for (int nt = 0; nt < 8; nt++)
#pragma unroll
            for (int q = 0; q < 4; q++) S[nt][q] = 0.f;

#pragma unroll 4
        for (int k8 = 0; k8 < 16; k8++) {
            uint32_t qa[4];
            ldsm_x4(qa, QsB + qOff + k8 * 32);
#pragma unroll
            for (int p = 0; p < 4; p++) {
                uint32_t kb[4];
                ldsm_x4(kb, KtB + kOff[p] + k8 * 32);
                mma_m16n8k8_tf32(S[2 * p], qa, kb[0], kb[1]);
                mma_m16n8k8_tf32(S[2 * p + 1], qa, kb[2], kb[3]);
            }
        }

        const bool fullvis = (!diag) & (dqFirst == dqLast)
                             & (dqFirst == dock[0]) & (dock[0] == dock[KTL - 1]);

        float mx0 = -3.0e38f, mx1 = -3.0e38f;
        if (fullvis) {
#pragma unroll
            for (int nt = 0; nt < 8; nt++) {
                S[nt][0] *= SCALE; S[nt][1] *= SCALE;
                S[nt][2] *= SCALE; S[nt][3] *= SCALE;
                mx0 = fmaxf(mx0, fmaxf(S[nt][0], S[nt][1]));
                mx1 = fmaxf(mx1, fmaxf(S[nt][2], S[nt][3]));
            }
        } else {
#pragma unroll
            for (int nt = 0; nt < 8; nt++) {
                int cl = nt * 8 + 2 * lc;
                int2 dk = *(const int2*)&dock[cl];
                int gc0 = k0tok + cl, gc1 = gc0 + 1;
                bool ok00 = (dk.x == dq0) && (!diag || gc0 <= r0g);
                bool ok01 = (dk.y == dq0) && (!diag || gc1 <= r0g);
                bool ok10 = (dk.x == dq1) && (!diag || gc0 <= r1g);
                bool ok11 = (dk.y == dq1) && (!diag || gc1 <= r1g);
                S[nt][0] = ok00 ? S[nt][0] * SCALE : -1.7e38f;
                S[nt][1] = ok01 ? S[nt][1] * SCALE : -1.7e38f;
                S[nt][2] = ok10 ? S[nt][2] * SCALE : -1.7e38f;
                S[nt][3] = ok11 ? S[nt][3] * SCALE : -1.7e38f;
                mx0 = fmaxf(mx0, fmaxf(S[nt][0], S[nt][1]));
                mx1 = fmaxf(mx1, fmaxf(S[nt][2], S[nt][3]));
            }
        }
        mx0 = fmaxf(mx0, __shfl_xor_sync(0xffffffffu, mx0, 1));
        mx0 = fmaxf(mx0, __shfl_xor_sync(0xffffffffu, mx0, 2));
        mx1 = fmaxf(mx1, __shfl_xor_sync(0xffffffffu, mx1, 1));
        mx1 = fmaxf(mx1, __shfl_xor_sync(0xffffffffu, mx1, 2));

        float mn0 = fmaxf(m0, mx0), mn1 = fmaxf(m1, mx1);
        float al0 = __expf(m0 - mn0), al1 = __expf(m1 - mn1);
        float sum0 = 0.f, sum1 = 0.f;
#pragma unroll
        for (int nt = 0; nt < 8; nt++) {
            float p00 = __expf(S[nt][0] - mn0);
            float p01 = __expf(S[nt][1] - mn0);
            float p10 = __expf(S[nt][2] - mn1);
            float p11 = __expf(S[nt][3] - mn1);
            sum0 += p00 + p01;
            sum1 += p10 + p11;
            Su[nt * 4 + 0] = to_tf32_bits(p00);
            Su[nt * 4 + 1] = to_tf32_bits(p01);
            Su[nt * 4 + 2] = to_tf32_bits(p10);
            Su[nt * 4 + 3] = to_tf32_bits(p11);
        }
        sum0 += __shfl_xor_sync(0xffffffffu, sum0, 1);
        sum0 += __shfl_xor_sync(0xffffffffu, sum0, 2);
        sum1 += __shfl_xor_sync(0xffffffffu, sum1, 1);
        sum1 += __shfl_xor_sync(0xffffffffu, sum1, 2);
        l0 = l0 * al0 + sum0; m0 = mn0;
        l1 = l1 * al1 + sum1; m1 = mn1;
#pragma unroll
        for (int nt = 0; nt < 16; nt++) {
            O[nt][0] *= al0; O[nt][1] *= al0;
            O[nt][2] *= al1; O[nt][3] *= al1;
        }

        asm volatile("cp.async.wait_group 0;" ::: "memory");
        __syncthreads();

        if (kt < qt) issueK(kt + 1);
        asm volatile("cp.async.commit_group;" ::: "memory");

#pragma unroll 4
        for (int k8 = 0; k8 < 8; k8++) {
            uint32_t pa[4];
            {
                uint32_t u0 = __shfl_sync(0xffffffffu, Su[k8 * 4 + 0], sl1);
                uint32_t u1 = __shfl_sync(0xffffffffu, Su[k8 * 4 + 1], sl1);
                uint32_t u2 = __shfl_sync(0xffffffffu, Su[k8 * 4 + 2], sl1);
                uint32_t u3 = __shfl_sync(0xffffffffu, Su[k8 * 4 + 3], sl1);
                uint32_t v0 = __shfl_sync(0xffffffffu, Su[k8 * 4 + 0], sl2);
                uint32_t v1 = __shfl_sync(0xffffffffu, Su[k8 * 4 + 1], sl2);
                uint32_t v2 = __shfl_sync(0xffffffffu, Su[k8 * 4 + 2], sl2);
                uint32_t v3 = __shfl_sync(0xffffffffu, Su[k8 * 4 + 3], sl2);
                pa[0] = odd ? u1 : u0;
                pa[1] = odd ? u3 : u2;
                pa[2] = odd ? v1 : v0;
                pa[3] = odd ? v3 : v2;
            }
#pragma unroll
            for (int p = 0; p < 8; p++) {
                uint32_t vb[4];
                ldsm_x4(vb, VtB + vOff[p] + k8 * 32);
                mma_m16n8k8_tf32(O[2 * p], pa, vb[0], vb[1]);
                mma_m16n8k8_tf32(O[2 * p + 1], pa, vb[2], vb[3]);
            }
        }
        __syncthreads();

        if (kt < qt) issueV(kt + 1);
        asm volatile("cp.async.commit_group;" ::: "memory");
    }

    float inv0 = 1.0f / l0, inv1 = 1.0f / l1;
    float* out0 = outa + (size_t)(b * TSEQ + r0g) * DMODEL + h * HDIM;
    float* out1 = outa + (size_t)(b * TSEQ + r1g) * DMODEL + h * HDIM;
#pragma unroll
    for (int nt = 0; nt < 16; nt++) {
        int cl = nt * 8 + 2 * lc;
        *(float2*)(out0 + cl) = make_float2(to_tf32(O[nt][0] * inv0),
                                            to_tf32(O[nt][1] * inv0));
        *(float2*)(out1 + cl) = make_float2(to_tf32(O[nt][2] * inv1),
                                            to_tf32(O[nt][3] * inv1));
    }
}

// ---------------------------------------------------------------------------
extern "C" void kernel_launch(void* const* d_in, const int* in_sizes, int n_in,
                              void* d_out, int out_size)
{
    const float* x    = (const float*)d_in[0];
    const float* sinp = (const float*)d_in[1];
    const float* cosp = (const float*)d_in[2];
    const int*   doc  = (const int*)d_in[3];
    const float* Wqkv = (const float*)d_in[4];
    const float* Wout = (const float*)d_in[5];
    float* out = (float*)d_out;

    float *qkv, *attn, *xr, *vT, *wqkv_t, *wout_t;
    cudaGetSymbolAddress((void**)&qkv,    g_qkv);
    cudaGetSymbolAddress((void**)&attn,   g_attn);
    cudaGetSymbolAddress((void**)&xr,     g_xr);
    cudaGetSymbolAddress((void**)&vT,     g_vT);
    cudaGetSymbolAddress((void**)&wqkv_t, g_wqkv_t);
    cudaGetSymbolAddress((void**)&wout_t, g_wout_t);

    cudaFuncSetAttribute(gemm_mma_tf32<true>,
                         cudaFuncAttributeMaxDynamicSharedMemorySize, GEMM_SMEM);
    cudaFuncSetAttribute(gemm_mma_tf32<false>,
                         cudaFuncAttributeMaxDynamicSharedMemorySize, GEMM_SMEM);
    cudaFuncSetAttribute(attn_mma,
                         cudaFuncAttributeMaxDynamicSharedMemorySize, ATT_SMEM_BYTES);

    // 0) merged prep: both weight transposes + x rounding in one launch
    {
        dim3 bdim(32, 8);
        prep_all<<<16896, bdim>>>(Wqkv, wqkv_t, Wout, wout_t, x, xr);
    }

    // 1) qkv = xr @ W_qkv; fused rope (bn<2176), V->vT (bn==2176), rounded
    {
        dim3 g(QKVW / 128, MROWS / 128);
        gemm_mma_tf32<true><<<g, 128, GEMM_SMEM>>>(
            xr, wqkv_t, qkv, sinp, cosp, vT,
            MROWS, QKVW, DMODEL, DMODEL + HDIM, DMODEL + HDIM);
    }

    // 2) flash attention
    {
        dim3 g(TSEQ / QTL, NHEADS, BATCH);
        attn_mma<<<g, 128, ATT_SMEM_BYTES>>>(qkv, vT, doc, attn);
    }

    // 3) out = attn @ W_out (plain epilogue)
    {
        dim3 g(DMODEL / 128, MROWS / 128);
        gemm_mma_tf32<false><<<g, 128, GEMM_SMEM>>>(
            attn, wout_t, out, nullptr, nullptr, nullptr,
            MROWS, DMODEL, DMODEL, 0, -1);
    }
}

// round 17
// speedup vs baseline: 1.0567x; 1.0567x over previous
#include <cuda_runtime.h>
#include <math.h>
#include <stdint.h>

#define TSEQ   2048
#define DMODEL 2048
#define NHEADS 16
#define HDIM   128
#define BATCH  2
#define QKVW   (DMODEL + 2*HDIM)   // 2304
#define MROWS  (BATCH*TSEQ)        // 4096

__device__ float g_qkv   [(size_t)BATCH * TSEQ * QKVW];
__device__ float g_attn  [(size_t)BATCH * TSEQ * DMODEL];
__device__ float g_xr    [(size_t)BATCH * TSEQ * DMODEL];
__device__ float g_vT    [(size_t)BATCH * HDIM * TSEQ];
__device__ float g_wqkv_t[(size_t)QKVW * DMODEL];
__device__ float g_wout_t[(size_t)DMODEL * DMODEL];

// ---------------------------------------------------------------------------
__device__ __forceinline__ uint32_t smem_u32(const void* p) {
    uint32_t a;
    asm("{ .reg .u64 t; cvta.to.shared.u64 t, %1; cvt.u32.u64 %0, t; }"
        : "=r"(a) : "l"(p));
    return a;
}
__device__ __forceinline__ float to_tf32(float x) {
    uint32_t u;
    asm("cvt.rna.tf32.f32 %0, %1;" : "=r"(u) : "f"(x));
    return __uint_as_float(u);
}
__device__ __forceinline__ uint32_t to_tf32_bits(float x) {
    uint32_t u;
    asm("cvt.rna.tf32.f32 %0, %1;" : "=r"(u) : "f"(x));
    return u;
}
__device__ __forceinline__ void mma_m16n8k8_tf32(float* c, const uint32_t* a,
                                                 uint32_t b0, uint32_t b1) {
    asm volatile(
        "mma.sync.aligned.m16n8k8.row.col.f32.tf32.tf32.f32 "
        "{%0,%1,%2,%3}, {%4,%5,%6,%7}, {%8,%9}, {%0,%1,%2,%3};"
        : "+f"(c[0]), "+f"(c[1]), "+f"(c[2]), "+f"(c[3])
        : "r"(a[0]), "r"(a[1]), "r"(a[2]), "r"(a[3]), "r"(b0), "r"(b1));
}
__device__ __forceinline__ void ldsm_x4(uint32_t* r, uint32_t addr) {
    asm volatile("ldmatrix.sync.aligned.m8n8.x4.shared.b16 {%0,%1,%2,%3}, [%4];"
                 : "=r"(r[0]), "=r"(r[1]), "=r"(r[2]), "=r"(r[3]) : "r"(addr));
}

#define MBAR_INIT(a, n) \
    asm volatile("mbarrier.init.shared.b64 [%0], %1;" :: "r"(a), "r"(n) : "memory")
#define MBAR_ARRIVE(a) \
    asm volatile("mbarrier.arrive.shared.b64 _, [%0];" :: "r"(a) : "memory")
#define MBAR_WAIT(a, ph) do { \
    uint32_t _m = (a), _p = (ph), _d; \
    asm volatile("{ .reg .pred p; mbarrier.try_wait.parity.acquire.cta.shared::cta.b64 p, [%1], %2; selp.b32 %0,1,0,p; }" \
                 : "=r"(_d) : "r"(_m), "r"(_p) : "memory"); \
    if (!_d) { \
        asm volatile("{ .reg .pred P1; WL_%=: mbarrier.try_wait.parity.acquire.cta.shared::cta.b64 P1, [%0], %1, 0x989680; @P1 bra.uni WD_%=; bra.uni WL_%=; WD_%=: }" \
                     :: "r"(_m), "r"(_p) : "memory"); \
    } \
} while (0)
#define CPASYNC_MBAR_ARRIVE(a) \
    asm volatile("cp.async.mbarrier.arrive.noinc.shared.b64 [%0];" :: "r"(a) : "memory")

// ---------------------------------------------------------------------------
// Merged prep: Wqkv^T (blocks 0..4607), Wout^T (4608..8703), x round (rest).
// ---------------------------------------------------------------------------
__global__ void prep_all(const float* __restrict__ Wqkv, float* __restrict__ wqkv_t,
                         const float* __restrict__ Wout, float* __restrict__ wout_t,
                         const float* __restrict__ x, float* __restrict__ xr)
{
    __shared__ float t[32][33];
    const int blk = blockIdx.x;
    const int tx = threadIdx.x, ty = threadIdx.y;

    if (blk < 4608) {
        int n0 = (blk % 72) * 32, k0 = (blk / 72) * 32;
#pragma unroll
        for (int r = 0; r < 32; r += 8)
            t[ty + r][tx] = Wqkv[(size_t)(k0 + ty + r) * QKVW + n0 + tx];
        __syncthreads();
#pragma unroll
        for (int r = 0; r < 32; r += 8)
            wqkv_t[(size_t)(n0 + ty + r) * DMODEL + k0 + tx] = to_tf32(t[tx][ty + r]);
    } else if (blk < 8704) {
        int b2 = blk - 4608;
        int n0 = (b2 % 64) * 32, k0 = (b2 / 64) * 32;
#pragma unroll
        for (int r = 0; r < 32; r += 8)
            t[ty + r][tx] = Wout[(size_t)(k0 + ty + r) * DMODEL + n0 + tx];
        __syncthreads();
#pragma unroll
        for (int r = 0; r < 32; r += 8)
            wout_t[(size_t)(n0 + ty + r) * DMODEL + k0 + tx] = to_tf32(t[tx][ty + r]);
    } else {
        int i = (blk - 8704) * 256 + ty * 32 + tx;
        float4 v = ((const float4*)x)[i];
        v.x = to_tf32(v.x); v.y = to_tf32(v.y);
        v.z = to_tf32(v.z); v.w = to_tf32(v.w);
        ((float4*)xr)[i] = v;
    }
}

// ---------------------------------------------------------------------------
// mma.sync tf32 GEMM (round-15 proven: 256 thr, 8 warps 4x2, warp tile 32x64).
//  FUSED=false: byte-exact round-7 kernel (GEMM2).
//  FUSED=true : GEMM1 — fused rope (bn<rope_lim), V tile -> vT (bn==vt_col),
//               tf32-rounded stores. Mainloop identical in both.
// ---------------------------------------------------------------------------
#define BK 32
#define AS_STRIDE 36
#define TILE_FLOATS (128 * AS_STRIDE)
#define TILE_BYTES  (TILE_FLOATS * 4)
#define NSTAGE 3
#define GEMM_SMEM (2 * NSTAGE * TILE_BYTES + 64)

template<bool FUSED>
__global__ __launch_bounds__(256, 2) void gemm_mma_tf32(
    const float* __restrict__ A, const float* __restrict__ Bt,
    float* __restrict__ C,
    const float* __restrict__ sinp, const float* __restrict__ cosp,
    float* __restrict__ vTout,
    int M, int N, int K, int rope_lim, int vt_col)
{
    extern __shared__ float smf[];
    const uint32_t sm0 = smem_u32(smf);
    const uint32_t mb0 = sm0 + 2 * NSTAGE * TILE_BYTES;

    const int tid  = threadIdx.x;
    const int wid  = tid >> 5, lane = tid & 31;
    const int wm   = wid & 3, wn = wid >> 2;
    const int lr   = lane >> 2, lc = lane & 3;
    const int bm   = blockIdx.y * 128, bn = blockIdx.x * 128;
    const int NC   = K / BK;

    if (tid == 0) {
#pragma unroll
        for (int s = 0; s < NSTAGE; s++) {
            MBAR_INIT(mb0 + s * 8, 256);
            MBAR_INIT(mb0 + 24 + s * 8, 8);
        }
    }
    __syncthreads();

    const uint32_t aOff0 = ((uint32_t)((wm * 32 + (lane & 7) + ((lane >> 3) & 1) * 8)
                            * AS_STRIDE + (lane >> 4) * 4)) * 4;
    const uint32_t aOff1 = aOff0 + 16 * AS_STRIDE * 4;
    uint32_t bOff[4];
#pragma unroll
    for (int p = 0; p < 4; p++) {
        int rb = FUSED ? (wn * 32 + (p & 1) * 16 + (p >> 1) * 64)
                       : (wn * 64 + p * 16);
        bOff[p] = ((uint32_t)((rb + (lane & 7) + ((lane >> 4) & 1) * 8)
                   * AS_STRIDE + ((lane >> 3) & 1) * 4)) * 4;
    }

    float acc[2][8][4];
#pragma unroll
    for (int i = 0; i < 2; i++)
#pragma unroll
        for (int j = 0; j < 8; j++)
#pragma unroll
            for (int q = 0; q < 4; q++) acc[i][j][q] = 0.f;

    const int ldrow = tid >> 3, ldc4 = tid & 7;
    auto produce = [&](int s, int k0) {
        uint32_t sA = sm0 + s * TILE_BYTES;
        uint32_t sB = sm0 + (NSTAGE + s) * TILE_BYTES;
#pragma unroll
        for (int it = 0; it < 4; it++) {
            int row = it * 32 + ldrow;
            const float* g = A + (size_t)(bm + row) * K + k0 + ldc4 * 4;
            asm volatile("cp.async.cg.shared.global [%0], [%1], 16;"
                         :: "r"(sA + (uint32_t)(row * 144 + ldc4 * 16)), "l"(g));
        }
#pragma unroll
        for (int it = 0; it < 4; it++) {
            int row = it * 32 + ldrow;
            const float* g = Bt + (size_t)(bn + row) * K + k0 + ldc4 * 4;
            asm volatile("cp.async.cg.shared.global [%0], [%1], 16;"
                         :: "r"(sB + (uint32_t)(row * 144 + ldc4 * 16)), "l"(g));
        }
        CPASYNC_MBAR_ARRIVE(mb0 + s * 8);
    };

    produce(0, 0);
    produce(1, BK);
    produce(2, 2 * BK);

    int s = 0, ph = 0;
    for (int c = 0; c < NC; c++) {
        MBAR_WAIT(mb0 + s * 8, (uint32_t)ph);

        const uint32_t aBase = sm0 + s * TILE_BYTES;
        const uint32_t bBase = sm0 + (NSTAGE + s) * TILE_BYTES;
#pragma unroll
        for (int ks = 0; ks < 4; ks++) {
            uint32_t a0[4], a1[4], bb[16];
            ldsm_x4(a0, aBase + aOff0 + ks * 32);
            ldsm_x4(a1, aBase + aOff1 + ks * 32);
#pragma unroll
            for (int p = 0; p < 4; p++)
                ldsm_x4(&bb[4 * p], bBase + bOff[p] + ks * 32);
#pragma unroll
            for (int nt = 0; nt < 8; nt++) {
                mma_m16n8k8_tf32(acc[0][nt], a0, bb[2 * nt], bb[2 * nt + 1]);
                mma_m16n8k8_tf32(acc[1][nt], a1, bb[2 * nt], bb[2 * nt + 1]);
            }
        }
        if (lane == 0) MBAR_ARRIVE(mb0 + 24 + s * 8);

        if (c + NSTAGE < NC) {
            MBAR_WAIT(mb0 + 24 + s * 8, (uint32_t)ph);
            produce(s, (c + NSTAGE) * BK);
        }
        s++; if (s == NSTAGE) { s = 0; ph ^= 1; }
    }

    // ---------------- epilogue ----------------
    if (!FUSED) {
#pragma unroll
        for (int mt = 0; mt < 2; mt++) {
            int row = bm + wm * 32 + mt * 16 + lr;
#pragma unroll
            for (int nt = 0; nt < 8; nt++) {
                int col = bn + wn * 64 + nt * 8 + lc * 2;
                *(float2*)(C + (size_t)row * N + col) =
                    make_float2(acc[mt][nt][0], acc[mt][nt][1]);
                *(float2*)(C + (size_t)(row + 8) * N + col) =
                    make_float2(acc[mt][nt][2], acc[mt][nt][3]);
            }
        }
        return;
    }

    if (bn == vt_col) {
        __syncthreads();
        float* st = smf;   // [128 cols][136]
#pragma unroll
        for (int mt = 0; mt < 2; mt++) {
            int r0l = wm * 32 + mt * 16 + lr;
#pragma unroll
            for (int nt = 0; nt < 8; nt++) {
                int cl = wn * 32 + (nt >> 2) * 64 + ((nt >> 1) & 1) * 16
                         + (nt & 1) * 8 + lc * 2;
                st[cl * 136 + r0l]           = to_tf32(acc[mt][nt][0]);
                st[(cl + 1) * 136 + r0l]     = to_tf32(acc[mt][nt][1]);
                st[cl * 136 + r0l + 8]       = to_tf32(acc[mt][nt][2]);
                st[(cl + 1) * 136 + r0l + 8] = to_tf32(acc[mt][nt][3]);
            }
        }
        __syncthreads();
        const int bb_ = bm / TSEQ;
        const int t0 = bm & (TSEQ - 1);
#pragma unroll
        for (int it = 0; it < 16; it++) {
            int d = it * 8 + (tid >> 5);
            int t4 = (tid & 31) * 4;
            float4 v = *(float4*)&st[d * 136 + t4];
            *(float4*)&vTout[((size_t)bb_ * HDIM + d) * TSEQ + t0 + t4] = v;
        }
        return;
    }

    if (bn < rope_lim) {
#pragma unroll
        for (int mt = 0; mt < 2; mt++) {
            int row0 = bm + wm * 32 + mt * 16 + lr;
            int tA = row0 & (TSEQ - 1);
            int tB = (row0 + 8) & (TSEQ - 1);
#pragma unroll
            for (int nt = 0; nt < 4; nt++) {
                int i0 = wn * 32 + ((nt >> 1) & 1) * 16 + (nt & 1) * 8 + lc * 2;
                float2 sA = *(const float2*)&sinp[tA * 64 + i0];
                float2 cA = *(const float2*)&cosp[tA * 64 + i0];
                float2 sB = *(const float2*)&sinp[tB * 64 + i0];
                float2 cB = *(const float2*)&cosp[tB * 64 + i0];
                float x1, x2;
                x1 = acc[mt][nt][0]; x2 = acc[mt][nt + 4][0];
                acc[mt][nt][0]     = x1 * cA.x - x2 * sA.x;
                acc[mt][nt + 4][0] = x2 * cA.x + x1 * sA.x;
                x1 = acc[mt][nt][1]; x2 = acc[mt][nt + 4][1];
                acc[mt][nt][1]     = x1 * cA.y - x2 * sA.y;
                acc[mt][nt + 4][1] = x2 * cA.y + x1 * sA.y;
                x1 = acc[mt][nt][2]; x2 = acc[mt][nt + 4][2];
                acc[mt][nt][2]     = x1 * cB.x - x2 * sB.x;
                acc[mt][nt + 4][2] = x2 * cB.x + x1 * sB.x;
                x1 = acc[mt][nt][3]; x2 = acc[mt][nt + 4][3];
                acc[mt][nt][3]     = x1 * cB.y - x2 * sB.y;
                acc[mt][nt + 4][3] = x2 * cB.y + x1 * sB.y;
            }
        }
    }

#pragma unroll
    for (int mt = 0; mt < 2; mt++) {
        int row = bm + wm * 32 + mt * 16 + lr;
#pragma unroll
        for (int nt = 0; nt < 8; nt++) {
            int col = bn + wn * 32 + (nt >> 2) * 64
                      + ((nt >> 1) & 1) * 16 + (nt & 1) * 8 + lc * 2;
            *(float2*)(C + (size_t)row * N + col) =
                make_float2(to_tf32(acc[mt][nt][0]), to_tf32(acc[mt][nt][1]));
            *(float2*)(C + (size_t)(row + 8) * N + col) =
                make_float2(to_tf32(acc[mt][nt][2]), to_tf32(acc[mt][nt][3]));
        }
    }
}

// ---------------------------------------------------------------------------
// Flash attention (round-15 version, unchanged).
// ---------------------------------------------------------------------------
#define QTL 64
#define KTL 64
#define QST 132
#define VST 68
#define ATT_Q_OFF   0
#define ATT_K_OFF   (QTL * QST)
#define ATT_V_OFF   (2 * QTL * QST)
#define ATT_DOC_OFF (2 * QTL * QST + HDIM * VST)
#define ATT_SMEM_BYTES ((ATT_DOC_OFF + 132) * 4)

__global__ __launch_bounds__(128, 2) void attn_mma(
    const float* __restrict__ qkv, const float* __restrict__ vT,
    const int* __restrict__ doc, float* __restrict__ outa)
{
    extern __shared__ float smf[];
    int* docq  = (int*)(smf + ATT_DOC_OFF);
    int* dock  = docq + 64;
    int* skst  = dock + 64;

    const int tid = threadIdx.x;
    const int wid = tid >> 5, lane = tid & 31;
    const int lr = lane >> 2, lc = lane & 3;
    const int qt = blockIdx.x, h = blockIdx.y, b = blockIdx.z;
    const int q0 = qt * QTL;
    const float* qbase = qkv + (size_t)b * TSEQ * QKVW;
    const float* vbase = vT + (size_t)b * HDIM * TSEQ;
    const float SCALE = 0.08838834764831845f;

    const uint32_t sm0 = smem_u32(smf);
    const uint32_t QsB = sm0 + ATT_Q_OFF * 4;
    const uint32_t KtB = sm0 + ATT_K_OFF * 4;
    const uint32_t VtB = sm0 + ATT_V_OFF * 4;

    const uint32_t qOff = ((uint32_t)((wid * 16 + (lane & 7) + ((lane >> 3) & 1) * 8)
                           * QST + (lane >> 4) * 4)) * 4;
    uint32_t kOff[4];
#pragma unroll
    for (int p = 0; p < 4; p++)
        kOff[p] = ((uint32_t)((p * 16 + (lane & 7) + ((lane >> 4) & 1) * 8)
                   * QST + ((lane >> 3) & 1) * 4)) * 4;
    uint32_t vOff[8];
#pragma unroll
    for (int p = 0; p < 8; p++)
        vOff[p] = ((uint32_t)((p * 16 + (lane & 7) + ((lane >> 4) & 1) * 8)
                   * VST + ((lane >> 3) & 1) * 4)) * 4;

    const int sl1 = lr * 4 + (lc >> 1);
    const int sl2 = sl1 + 2;
    const bool odd = (lc & 1);

    const int qkRow = tid >> 5, qkChunk = (tid & 31);
    const int vRow = tid >> 4,  vChunk = (tid & 15);

#pragma unroll
    for (int r = 0; r < 16; r++) {
        int row = r * 4 + qkRow;
        const float* g = qbase + (size_t)(q0 + row) * QKVW + h * HDIM + qkChunk * 4;
        asm volatile("cp.async.cg.shared.global [%0], [%1], 16;"
                     :: "r"(QsB + (uint32_t)(row * (QST * 4) + qkChunk * 16)), "l"(g));
    }
    asm volatile("cp.async.commit_group;" ::: "memory");

    if (tid < 64) docq[tid] = doc[b * TSEQ + q0 + tid];
    if (tid == 0) {
        int d0 = doc[b * TSEQ + q0];
        int lo = 0, hi = q0;
        while (lo < hi) {
            int mid = (lo + hi) >> 1;
            if (doc[b * TSEQ + mid] < d0) lo = mid + 1; else hi = mid;
        }
        skst[0] = lo >> 6;
    }
    asm volatile("cp.async.wait_group 0;" ::: "memory");
    __syncthreads();

    const int kt_start = skst[0];
    const int r0g = q0 + wid * 16 + lr;
    const int r1g = r0g + 8;
    const int dq0 = docq[wid * 16 + lr];
    const int dq1 = docq[wid * 16 + lr + 8];
    const int dqFirst = docq[0], dqLast = docq[QTL - 1];

    auto issueK = [&](int kt) {
        const int k0 = kt * KTL;
#pragma unroll
        for (int r = 0; r < 16; r++) {
            int row = r * 4 + qkRow;
            const float* g = qbase + (size_t)(k0 + row) * QKVW + DMODEL + qkChunk * 4;
            asm volatile("cp.async.cg.shared.global [%0], [%1], 16;"
                         :: "r"(KtB + (uint32_t)(row * (QST * 4) + qkChunk * 16)), "l"(g));
        }
    };
    auto issueV = [&](int kt) {
        const int k0 = kt * KTL;
#pragma unroll
        for (int r = 0; r < 16; r++) {
            int d = r * 8 + vRow;
            const float* g = vbase + (size_t)d * TSEQ + k0 + vChunk * 4;
            asm volatile("cp.async.cg.shared.global [%0], [%1], 16;"
                         :: "r"(VtB + (uint32_t)(d * (VST * 4) + vChunk * 16)), "l"(g));
        }
    };

    float m0 = -1e30f, m1 = -1e30f, l0 = 0.f, l1 = 0.f;
    float O[16][4];
#pragma unroll
    for (int nt = 0; nt < 16; nt++)
#pragma unroll
        for (int q = 0; q < 4; q++) O[nt][q] = 0.f;

    issueK(kt_start);
    asm volatile("cp.async.commit_group;" ::: "memory");
    issueV(kt_start);
    asm volatile("cp.async.commit_group;" ::: "memory");

    for (int kt = kt_start; kt <= qt; kt++) {
        const int k0tok = kt * KTL;
        const bool diag = (kt == qt);

        if (tid < 64) dock[tid] = doc[b * TSEQ + k0tok + tid];

        asm volatile("cp.async.wait_group 1;" ::: "memory");
        __syncthreads();

        float S[8][4];
        uint32_t* Su = (uint32_t*)S;
#pragma unroll
        for (int nt = 0; nt < 8; nt++)
#pragma unroll
            for (int q = 0; q < 4; q++) S[nt][q] = 0.f;

#pragma unroll 4
        for (int k8 = 0; k8 < 16; k8++) {
            uint32_t qa[4];
            ldsm_x4(qa, QsB + qOff + k8 * 32);
#pragma unroll
            for (int p = 0; p < 4; p++) {
                uint32_t kb[4];
                ldsm_x4(kb, KtB + kOff[p] + k8 * 32);
                mma_m16n8k8_tf32(S[2 * p], qa, kb[0], kb[1]);
                mma_m16n8k8_tf32(S[2 * p + 1], qa, kb[2], kb[3]);
            }
        }

        const bool fullvis = (!diag) & (dqFirst == dqLast)
                             & (dqFirst == dock[0]) & (dock[0] == dock[KTL - 1]);

        float mx0 = -3.0e38f, mx1 = -3.0e38f;
        if (fullvis) {
#pragma unroll
            for (int nt = 0; nt < 8; nt++) {
                S[nt][0] *= SCALE; S[nt][1] *= SCALE;
                S[nt][2] *= SCALE; S[nt][3] *= SCALE;
                mx0 = fmaxf(mx0, fmaxf(S[nt][0], S[nt][1]));
                mx1 = fmaxf(mx1, fmaxf(S[nt][2], S[nt][3]));
            }
        } else {
#pragma unroll
            for (int nt = 0; nt < 8; nt++) {
                int cl = nt * 8 + 2 * lc;
                int2 dk = *(const int2*)&dock[cl];
                int gc0 = k0tok + cl, gc1 = gc0 + 1;
                bool ok00 = (dk.x == dq0) && (!diag || gc0 <= r0g);
                bool ok01 = (dk.y == dq0) && (!diag || gc1 <= r0g);
                bool ok10 = (dk.x == dq1) && (!diag || gc0 <= r1g);
                bool ok11 = (dk.y == dq1) && (!diag || gc1 <= r1g);
                S[nt][0] = ok00 ? S[nt][0] * SCALE : -1.7e38f;
                S[nt][1] = ok01 ? S[nt][1] * SCALE : -1.7e38f;
                S[nt][2] = ok10 ? S[nt][2] * SCALE : -1.7e38f;
                S[nt][3] = ok11 ? S[nt][3] * SCALE : -1.7e38f;
                mx0 = fmaxf(mx0, fmaxf(S[nt][0], S[nt][1]));
                mx1 = fmaxf(mx1, fmaxf(S[nt][2], S[nt][3]));
            }
        }
        mx0 = fmaxf(mx0, __shfl_xor_sync(0xffffffffu, mx0, 1));
        mx0 = fmaxf(mx0, __shfl_xor_sync(0xffffffffu, mx0, 2));
        mx1 = fmaxf(mx1, __shfl_xor_sync(0xffffffffu, mx1, 1));
        mx1 = fmaxf(mx1, __shfl_xor_sync(0xffffffffu, mx1, 2));

        float mn0 = fmaxf(m0, mx0), mn1 = fmaxf(m1, mx1);
        float al0 = __expf(m0 - mn0), al1 = __expf(m1 - mn1);
        float sum0 = 0.f, sum1 = 0.f;
#pragma unroll
        for (int nt = 0; nt < 8; nt++) {
            float p00 = __expf(S[nt][0] - mn0);
            float p01 = __expf(S[nt][1] - mn0);
            float p10 = __expf(S[nt][2] - mn1);
            float p11 = __expf(S[nt][3] - mn1);
            sum0 += p00 + p01;
            sum1 += p10 + p11;
            Su[nt * 4 + 0] = to_tf32_bits(p00);
            Su[nt * 4 + 1] = to_tf32_bits(p01);
            Su[nt * 4 + 2] = to_tf32_bits(p10);
            Su[nt * 4 + 3] = to_tf32_bits(p11);
        }
        sum0 += __shfl_xor_sync(0xffffffffu, sum0, 1);
        sum0 += __shfl_xor_sync(0xffffffffu, sum0, 2);
        sum1 += __shfl_xor_sync(0xffffffffu, sum1, 1);
        sum1 += __shfl_xor_sync(0xffffffffu, sum1, 2);
        l0 = l0 * al0 + sum0; m0 = mn0;
        l1 = l1 * al1 + sum1; m1 = mn1;
#pragma unroll
        for (int nt = 0; nt < 16; nt++) {
            O[nt][0] *= al0; O[nt][1] *= al0;
            O[nt][2] *= al1; O[nt][3] *= al1;
        }

        asm volatile("cp.async.wait_group 0;" ::: "memory");
        __syncthreads();

        if (kt < qt) issueK(kt + 1);
        asm volatile("cp.async.commit_group;" ::: "memory");

#pragma unroll 4
        for (int k8 = 0; k8 < 8; k8++) {
            uint32_t pa[4];
            {
                uint32_t u0 = __shfl_sync(0xffffffffu, Su[k8 * 4 + 0], sl1);
                uint32_t u1 = __shfl_sync(0xffffffffu, Su[k8 * 4 + 1], sl1);
                uint32_t u2 = __shfl_sync(0xffffffffu, Su[k8 * 4 + 2], sl1);
                uint32_t u3 = __shfl_sync(0xffffffffu, Su[k8 * 4 + 3], sl1);
                uint32_t v0 = __shfl_sync(0xffffffffu, Su[k8 * 4 + 0], sl2);
                uint32_t v1 = __shfl_sync(0xffffffffu, Su[k8 * 4 + 1], sl2);
                uint32_t v2 = __shfl_sync(0xffffffffu, Su[k8 * 4 + 2], sl2);
                uint32_t v3 = __shfl_sync(0xffffffffu, Su[k8 * 4 + 3], sl2);
                pa[0] = odd ? u1 : u0;
                pa[1] = odd ? u3 : u2;
                pa[2] = odd ? v1 : v0;
                pa[3] = odd ? v3 : v2;
            }
#pragma unroll
            for (int p = 0; p < 8; p++) {
                uint32_t vb[4];
                ldsm_x4(vb, VtB + vOff[p] + k8 * 32);
                mma_m16n8k8_tf32(O[2 * p], pa, vb[0], vb[1]);
                mma_m16n8k8_tf32(O[2 * p + 1], pa, vb[2], vb[3]);
            }
        }
        __syncthreads();

        if (kt < qt) issueV(kt + 1);
        asm volatile("cp.async.commit_group;" ::: "memory");
    }

    float inv0 = 1.0f / l0, inv1 = 1.0f / l1;
    float* out0 = outa + (size_t)(b * TSEQ + r0g) * DMODEL + h * HDIM;
    float* out1 = outa + (size_t)(b * TSEQ + r1g) * DMODEL + h * HDIM;
#pragma unroll
    for (int nt = 0; nt < 16; nt++) {
        int cl = nt * 8 + 2 * lc;
        *(float2*)(out0 + cl) = make_float2(to_tf32(O[nt][0] * inv0),
                                            to_tf32(O[nt][1] * inv0));
        *(float2*)(out1 + cl) = make_float2(to_tf32(O[nt][2] * inv1),
                                            to_tf32(O[nt][3] * inv1));
    }
}

// ---------------------------------------------------------------------------
extern "C" void kernel_launch(void* const* d_in, const int* in_sizes, int n_in,
                              void* d_out, int out_size)
{
    const float* x    = (const float*)d_in[0];
    const float* sinp = (const float*)d_in[1];
    const float* cosp = (const float*)d_in[2];
    const int*   doc  = (const int*)d_in[3];
    const float* Wqkv = (const float*)d_in[4];
    const float* Wout = (const float*)d_in[5];
    float* out = (float*)d_out;

    float *qkv, *attn, *xr, *vT, *wqkv_t, *wout_t;
    cudaGetSymbolAddress((void**)&qkv,    g_qkv);
    cudaGetSymbolAddress((void**)&attn,   g_attn);
    cudaGetSymbolAddress((void**)&xr,     g_xr);
    cudaGetSymbolAddress((void**)&vT,     g_vT);
    cudaGetSymbolAddress((void**)&wqkv_t, g_wqkv_t);
    cudaGetSymbolAddress((void**)&wout_t, g_wout_t);

    cudaFuncSetAttribute(gemm_mma_tf32<true>,
                         cudaFuncAttributeMaxDynamicSharedMemorySize, GEMM_SMEM);
    cudaFuncSetAttribute(gemm_mma_tf32<false>,
                         cudaFuncAttributeMaxDynamicSharedMemorySize, GEMM_SMEM);
    cudaFuncSetAttribute(attn_mma,
                         cudaFuncAttributeMaxDynamicSharedMemorySize, ATT_SMEM_BYTES);

    // 0) merged prep (both W^T + x rounding, one launch)
    {
        dim3 bdim(32, 8);
        prep_all<<<16896, bdim>>>(Wqkv, wqkv_t, Wout, wout_t, x, xr);
    }

    // 1) qkv = xr @ W_qkv; fused rope (bn<2176), V->vT (bn==2176), rounded
    {
        dim3 g(QKVW / 128, MROWS / 128);
        gemm_mma_tf32<true><<<g, 256, GEMM_SMEM>>>(
            xr, wqkv_t, qkv, sinp, cosp, vT,
            MROWS, QKVW, DMODEL, DMODEL + HDIM, DMODEL + HDIM);
    }

    // 2) flash attention
    {
        dim3 g(TSEQ / QTL, NHEADS, BATCH);
        attn_mma<<<g, 128, ATT_SMEM_BYTES>>>(qkv, vT, doc, attn);
    }

    // 3) out = attn @ W_out (plain round-7 kernel)
    {
        dim3 g(DMODEL / 128, MROWS / 128);
        gemm_mma_tf32<false><<<g, 256, GEMM_SMEM>>>(
            attn, wout_t, out, nullptr, nullptr, nullptr,
            MROWS, DMODEL, DMODEL, 0, -1);
    }
}